// round 1
// baseline (speedup 1.0000x reference)
#include <cuda_runtime.h>
#include <cstdint>

// ---------------- problem constants ----------------
#define K2    36864              // (CHEB_K*HIDDEN)^2
#define MTOT  1024               // N_NODE
#define NTOT  768                // H_FILTER
#define SPLIT 12                 // split-K factor
#define KS    (K2 / SPLIT)       // 3072 per split
#define BM    128
#define BN    128
#define BK    16
#define LDA   18                 // BK + 2 pad: conflict-free LDS.64 column reads
#define NIT   (KS / BK)          // 192 iterations

#define BATCH   64
#define T_IN    12
#define HORIZON 12
#define DDIM    64

// split-K partial sums: [SPLIT][MTOT][NTOT]
__device__ float g_scratch[SPLIT * MTOT * NTOT];

// ---------------- small helpers ----------------
static __device__ __forceinline__ void ffma2(unsigned long long& d,
                                             unsigned long long a,
                                             unsigned long long b) {
    // packed fp32x2 FMA (Blackwell FFMA2) — 2 MACs per instruction
    asm("fma.rn.f32x2 %0, %1, %2, %0;" : "+l"(d) : "l"(a), "l"(b));
}

static __device__ __forceinline__ unsigned long long lds_f2(const float* p) {
    return *reinterpret_cast<const unsigned long long*>(p);
}

static __device__ __forceinline__ void cp_async8(uint32_t dst, const void* src) {
    asm volatile("cp.async.ca.shared.global [%0], [%1], 8;\n" :: "r"(dst), "l"(src));
}
static __device__ __forceinline__ void cp_commit() {
    asm volatile("cp.async.commit_group;\n" ::: "memory");
}
template <int N>
static __device__ __forceinline__ void cp_wait() {
    asm volatile("cp.async.wait_group %0;\n" :: "n"(N) : "memory");
}

// global -> shared prefetch of one 128x16 A tile and one 128x16 B tile
static __device__ __forceinline__ void prefetch_tile(
    const float* __restrict__ Ab, const float* __restrict__ Bb, int it,
    uint32_t As_base, uint32_t Bs_base, int buf, int tid)
{
    const float* ag = Ab + (size_t)it * BK;
    const float* bg = Bb + (size_t)it * BK;
    uint32_t aoff = As_base + (uint32_t)buf * (BM * LDA * 4);
    uint32_t boff = Bs_base + (uint32_t)buf * (BN * LDA * 4);
    // 1024 8-byte ops per tile, 4 per thread; 8 threads cover one 64B row-chunk
    #pragma unroll
    for (int r = 0; r < 4; r++) {
        int o   = tid + 256 * r;
        int row = o >> 3;
        int u2  = (o & 7) * 2;                 // float offset within row (even)
        cp_async8(aoff + (uint32_t)(row * LDA + u2) * 4, ag + (size_t)row * K2 + u2);
        cp_async8(boff + (uint32_t)(row * LDA + u2) * 4, bg + (size_t)row * K2 + u2);
    }
    cp_commit();
}

// ---------------- kernel 1: split-K SGEMM (C = A * B^T), FFMA2 ----------------
// A = weights [MTOT][K2], B = W_hyp [NTOT][K2]; both K-contiguous (dot-product GEMM)
__global__ void __launch_bounds__(256, 1)
gemm_splitk_kernel(const float* __restrict__ A, const float* __restrict__ B)
{
    __shared__ float As[2][BM * LDA];
    __shared__ float Bs[2][BN * LDA];

    const int tid = threadIdx.x;
    const int tx  = tid & 15;     // column group (16)
    const int ty  = tid >> 4;     // row group (16)

    const int bm = blockIdx.x;    // 0..7
    const int bn = blockIdx.y;    // 0..5
    const int s  = blockIdx.z;    // 0..SPLIT-1

    const float* Ab = A + (size_t)(bm * BM) * K2 + (size_t)s * KS;
    const float* Bb = B + (size_t)(bn * BN) * K2 + (size_t)s * KS;

    const uint32_t As_base = (uint32_t)__cvta_generic_to_shared(&As[0][0]);
    const uint32_t Bs_base = (uint32_t)__cvta_generic_to_shared(&Bs[0][0]);

    unsigned long long acc[8][8];
    #pragma unroll
    for (int i = 0; i < 8; i++)
        #pragma unroll
        for (int j = 0; j < 8; j++) acc[i][j] = 0ull;

    prefetch_tile(Ab, Bb, 0, As_base, Bs_base, 0, tid);

    for (int it = 0; it < NIT; ++it) {
        const int buf = it & 1;
        if (it + 1 < NIT) {
            prefetch_tile(Ab, Bb, it + 1, As_base, Bs_base, buf ^ 1, tid);
            cp_wait<1>();        // current tile's group complete
        } else {
            cp_wait<0>();
        }
        __syncthreads();

        const float* Ak = &As[buf][0];
        const float* Bk = &Bs[buf][0];
        #pragma unroll
        for (int kk = 0; kk < BK; kk += 2) {
            unsigned long long a2[8], b2[8];
            #pragma unroll
            for (int i = 0; i < 8; i++) a2[i] = lds_f2(Ak + (ty + 16 * i) * LDA + kk);
            #pragma unroll
            for (int j = 0; j < 8; j++) b2[j] = lds_f2(Bk + (tx + 16 * j) * LDA + kk);
            #pragma unroll
            for (int i = 0; i < 8; i++)
                #pragma unroll
                for (int j = 0; j < 8; j++)
                    ffma2(acc[i][j], a2[i], b2[j]);
        }
        __syncthreads();   // protect buf^1 for next iteration's prefetch store
    }

    // epilogue: horizontal pair-sum, write split partials
    float* outp = g_scratch + ((size_t)s * MTOT + (size_t)bm * BM) * NTOT + bn * BN;
    #pragma unroll
    for (int i = 0; i < 8; i++) {
        const int row = ty + 16 * i;
        #pragma unroll
        for (int j = 0; j < 8; j++) {
            float2 v = *reinterpret_cast<float2*>(&acc[i][j]);
            outp[(size_t)row * NTOT + (tx + 16 * j)] = v.x + v.y;
        }
    }
}

// ---------------- kernel 2: split-K reduce + bias + einsum ----------------
// out[b,t,n] = sum_f x[b,n,f] * h[n,t,f],  x = output[:, T_IN-1]
__global__ void __launch_bounds__(256)
epilogue_kernel(const float* __restrict__ x_all,   // output [64][12][1024][64]
                const float* __restrict__ b_hyp,   // [768]
                float* __restrict__ out)           // [64][12][1024]
{
    __shared__ float sh_h[HORIZON * 65];   // [t][f], padded vs bank conflicts
    __shared__ float sh_x[BATCH * 65];     // [b][f], padded

    const int n   = blockIdx.x;            // node
    const int tid = threadIdx.x;

    // h[n, j] = sum_s scratch[s][n][j] + b_hyp[j]
    #pragma unroll
    for (int r = 0; r < 3; r++) {
        const int j = tid + 256 * r;        // 0..767
        float acc = b_hyp[j];
        #pragma unroll
        for (int s = 0; s < SPLIT; s++)
            acc += g_scratch[((size_t)s * MTOT + n) * NTOT + j];
        sh_h[(j >> 6) * 65 + (j & 63)] = acc;
    }

    // x[b, f] = output[b, 11, n, f]
    #pragma unroll
    for (int r = 0; r < 16; r++) {
        const int i = tid + 256 * r;        // 0..4095
        const int b = i >> 6, f = i & 63;
        sh_x[b * 65 + f] =
            x_all[((size_t)(b * T_IN + (T_IN - 1)) * MTOT + n) * DDIM + f];
    }
    __syncthreads();

    // 768 outputs per block (64 b x 12 t), 3 per thread
    #pragma unroll
    for (int r = 0; r < 3; r++) {
        const int j = tid + 256 * r;
        const int b = j / 12, t = j % 12;
        float acc = 0.0f;
        #pragma unroll
        for (int f = 0; f < 64; f++)
            acc += sh_x[b * 65 + f] * sh_h[t * 65 + f];
        out[(size_t)(b * HORIZON + t) * MTOT + n] = acc;
    }
}

// ---------------- launch ----------------
extern "C" void kernel_launch(void* const* d_in, const int* in_sizes, int n_in,
                              void* d_out, int out_size) {
    const float* output  = (const float*)d_in[0];   // [64,12,1024,64]
    const float* weights = (const float*)d_in[1];   // [1024,36864]
    const float* W_hyp   = (const float*)d_in[2];   // [768,36864]
    const float* b_hyp   = (const float*)d_in[3];   // [768]
    float* out = (float*)d_out;                     // [64,12,1024,1]

    dim3 grid(MTOT / BM, NTOT / BN, SPLIT);         // (8, 6, 12)
    gemm_splitk_kernel<<<grid, 256>>>(weights, W_hyp);
    epilogue_kernel<<<MTOT, 256>>>(output, b_hyp, out);
}

// round 3
// speedup vs baseline: 2.2798x; 2.2798x over previous
#include <cuda_runtime.h>
#include <cuda_bf16.h>
#include <cstdint>

// ---------------- problem constants ----------------
#define K2     36864
#define MTOT   1024
#define NTOT   768
#define SPLITK 3
#define KS     (K2 / SPLITK)      // 12288 k per CTA
#define BM     128
#define BN     128
#define BK     64                 // bf16 k per pipeline stage (128B rows)
#define NIT    (KS / BK)          // 192
#define NSTAGE 3

#define BATCH   64
#define T_IN    12
#define HORIZON 12

// ---------------- device scratch ----------------
__device__ __nv_bfloat16 g_Ahi[(size_t)MTOT * K2];
__device__ __nv_bfloat16 g_Alo[(size_t)MTOT * K2];
__device__ __nv_bfloat16 g_Bhi[(size_t)NTOT * K2];
__device__ __nv_bfloat16 g_Blo[(size_t)NTOT * K2];
__device__ float g_part[(size_t)SPLITK * MTOT * NTOT];   // [s][m][n]

// ---------------- SMEM layout ----------------
// per stage: Ahi 16K | Alo 16K | Bhi 16K | Blo 16K  = 64K; 3 stages = 192K
#define STAGE_BYTES 65536
#define OFF_AHI 0
#define OFF_ALO 16384
#define OFF_BHI 32768
#define OFF_BLO 49152
#define SMEM_TOTAL (NSTAGE * STAGE_BYTES)

// ---------------- helpers ----------------
static __device__ __forceinline__ void cpa16(uint32_t dst, const void* src) {
    asm volatile("cp.async.cg.shared.global [%0], [%1], 16;\n" :: "r"(dst), "l"(src));
}
static __device__ __forceinline__ void cp_commit() {
    asm volatile("cp.async.commit_group;\n" ::: "memory");
}

static __device__ __forceinline__ void ldsm4(uint32_t (&r)[4], uint32_t addr) {
    asm volatile("ldmatrix.sync.aligned.m8n8.x4.shared.b16 {%0,%1,%2,%3}, [%4];"
                 : "=r"(r[0]), "=r"(r[1]), "=r"(r[2]), "=r"(r[3]) : "r"(addr));
}

static __device__ __forceinline__ void mma16816(float (&d)[4], const uint32_t (&a)[4],
                                                uint32_t b0, uint32_t b1) {
    asm volatile("mma.sync.aligned.m16n8k16.row.col.f32.bf16.bf16.f32 "
                 "{%0,%1,%2,%3}, {%4,%5,%6,%7}, {%8,%9}, {%0,%1,%2,%3};"
                 : "+f"(d[0]), "+f"(d[1]), "+f"(d[2]), "+f"(d[3])
                 : "r"(a[0]), "r"(a[1]), "r"(a[2]), "r"(a[3]), "r"(b0), "r"(b1));
}

// ---------------- kernel 0: fp32 -> (bf16 hi, bf16 lo) ----------------
__global__ void __launch_bounds__(256)
convert_kernel(const float* __restrict__ src, int which, int n4) {
    int i = blockIdx.x * blockDim.x + threadIdx.x;
    if (i >= n4) return;
    __nv_bfloat16* hi = which ? g_Bhi : g_Ahi;
    __nv_bfloat16* lo = which ? g_Blo : g_Alo;
    float4 v = reinterpret_cast<const float4*>(src)[i];
    float f[4] = {v.x, v.y, v.z, v.w};
    __nv_bfloat162 h2[2], l2[2];
    #pragma unroll
    for (int k = 0; k < 4; k++) {
        __nv_bfloat16 h = __float2bfloat16(f[k]);
        __nv_bfloat16 l = __float2bfloat16(f[k] - __bfloat162float(h));
        if (k & 1) { h2[k >> 1].y = h; l2[k >> 1].y = l; }
        else       { h2[k >> 1].x = h; l2[k >> 1].x = l; }
    }
    reinterpret_cast<__nv_bfloat162*>(hi)[i * 2 + 0] = h2[0];
    reinterpret_cast<__nv_bfloat162*>(hi)[i * 2 + 1] = h2[1];
    reinterpret_cast<__nv_bfloat162*>(lo)[i * 2 + 0] = l2[0];
    reinterpret_cast<__nv_bfloat162*>(lo)[i * 2 + 1] = l2[1];
}

// ---------------- stage loader: 4096 x 16B cp.async, swizzled ----------------
static __device__ __forceinline__ void load_stage(
    uint32_t stb,
    const __nv_bfloat16* __restrict__ pAhi, const __nv_bfloat16* __restrict__ pAlo,
    const __nv_bfloat16* __restrict__ pBhi, const __nv_bfloat16* __restrict__ pBlo,
    int tid)
{
    #pragma unroll
    for (int i = 0; i < 16; i++) {
        const int idx    = i * 256 + tid;     // 0..4095
        const int region = idx >> 10;         // 0..3 (constant per i)
        const int chunk  = idx & 1023;
        const int row    = chunk >> 3;
        const int c      = chunk & 7;
        const __nv_bfloat16* gp =
            (region == 0) ? pAhi : (region == 1) ? pAlo : (region == 2) ? pBhi : pBlo;
        const uint32_t dst = stb + (uint32_t)(region * 16384)
                           + (uint32_t)(row * 128 + ((c ^ (row & 7)) << 4));
        cpa16(dst, gp + (size_t)row * K2 + c * 8);
    }
    cp_commit();
}

// ---------------- kernel 1: split-K GEMM via mma.sync bf16x3 ----------------
__global__ void __launch_bounds__(256, 1)
gemm_mma_kernel()
{
    extern __shared__ char smem[];
    const uint32_t sb = (uint32_t)__cvta_generic_to_shared(smem);
    const int tid  = threadIdx.x;
    const int lane = tid & 31;
    const int wid  = tid >> 5;
    const int wm   = (wid >> 1) * 32;    // warp row offset in tile (4 warps)
    const int wn   = (wid & 1) * 64;     // warp col offset in tile (2 warps)
    const int bm = blockIdx.x, bn = blockIdx.y, s = blockIdx.z;

    const size_t kbase = (size_t)s * KS;
    const __nv_bfloat16* pAhi = g_Ahi + (size_t)(bm * BM) * K2 + kbase;
    const __nv_bfloat16* pAlo = g_Alo + (size_t)(bm * BM) * K2 + kbase;
    const __nv_bfloat16* pBhi = g_Bhi + (size_t)(bn * BN) * K2 + kbase;
    const __nv_bfloat16* pBlo = g_Blo + (size_t)(bn * BN) * K2 + kbase;

    float acc[2][8][4];
    #pragma unroll
    for (int f = 0; f < 2; f++)
        #pragma unroll
        for (int j = 0; j < 8; j++)
            #pragma unroll
            for (int r = 0; r < 4; r++) acc[f][j][r] = 0.0f;

    // prologue: stages 0, 1
    load_stage(sb,               pAhi,      pAlo,      pBhi,      pBlo,      tid);
    load_stage(sb + STAGE_BYTES, pAhi + BK, pAlo + BK, pBhi + BK, pBlo + BK, tid);

    const int lr = lane & 15;     // ldmatrix row within 16
    const int lc = lane >> 4;     // ldmatrix k-half (0/1)

    for (int it = 0; it < NIT; ++it) {
        if (it + 2 < NIT) {
            const size_t ko = (size_t)(it + 2) * BK;
            load_stage(sb + ((it + 2) % NSTAGE) * STAGE_BYTES,
                       pAhi + ko, pAlo + ko, pBhi + ko, pBlo + ko, tid);
        } else {
            cp_commit();   // keep group accounting aligned
        }
        asm volatile("cp.async.wait_group 2;\n" ::: "memory");
        __syncthreads();

        const uint32_t stb = sb + (it % NSTAGE) * STAGE_BYTES;

        #pragma unroll
        for (int kk = 0; kk < 4; kk++) {          // 4 x k16 per stage
            uint32_t aHi[2][4], aLo[2][4];
            #pragma unroll
            for (int f = 0; f < 2; f++) {
                const int row = wm + f * 16 + lr;
                const int c   = kk * 2 + lc;
                const uint32_t off = (uint32_t)(row * 128 + ((c ^ (row & 7)) << 4));
                ldsm4(aHi[f], stb + OFF_AHI + off);
                ldsm4(aLo[f], stb + OFF_ALO + off);
            }
            uint32_t bHi[4][4], bLo[4][4];
            #pragma unroll
            for (int g = 0; g < 4; g++) {
                const int row = wn + g * 16 + lr;
                const int c   = kk * 2 + lc;
                const uint32_t off = (uint32_t)(row * 128 + ((c ^ (row & 7)) << 4));
                ldsm4(bHi[g], stb + OFF_BHI + off);
                ldsm4(bLo[g], stb + OFF_BLO + off);
            }
            // pass 1: Ahi * Bhi   (pass-major order keeps acc reuse distance = 16)
            #pragma unroll
            for (int f = 0; f < 2; f++)
                #pragma unroll
                for (int j = 0; j < 8; j++)
                    mma16816(acc[f][j], aHi[f], bHi[j >> 1][j & 1], bHi[j >> 1][(j & 1) + 2]);
            // pass 2: Ahi * Blo
            #pragma unroll
            for (int f = 0; f < 2; f++)
                #pragma unroll
                for (int j = 0; j < 8; j++)
                    mma16816(acc[f][j], aHi[f], bLo[j >> 1][j & 1], bLo[j >> 1][(j & 1) + 2]);
            // pass 3: Alo * Bhi
            #pragma unroll
            for (int f = 0; f < 2; f++)
                #pragma unroll
                for (int j = 0; j < 8; j++)
                    mma16816(acc[f][j], aLo[f], bHi[j >> 1][j & 1], bHi[j >> 1][(j & 1) + 2]);
        }
        __syncthreads();   // protect this stage's buffer before it is reloaded
    }

    // store partials: [s][m][n]
    float* base = g_part + ((size_t)s * MTOT + (size_t)bm * BM) * NTOT + bn * BN;
    #pragma unroll
    for (int f = 0; f < 2; f++) {
        const int r0 = wm + f * 16 + (lane >> 2);
        #pragma unroll
        for (int j = 0; j < 8; j++) {
            const int n0 = wn + j * 8 + (lane & 3) * 2;
            *reinterpret_cast<float2*>(&base[(size_t)r0 * NTOT + n0]) =
                make_float2(acc[f][j][0], acc[f][j][1]);
            *reinterpret_cast<float2*>(&base[(size_t)(r0 + 8) * NTOT + n0]) =
                make_float2(acc[f][j][2], acc[f][j][3]);
        }
    }
}

// ---------------- kernel 2: split-K reduce + bias + einsum ----------------
__global__ void __launch_bounds__(256)
epilogue_kernel(const float* __restrict__ x_all,   // output [64][12][1024][64]
                const float* __restrict__ b_hyp,   // [768]
                float* __restrict__ out)           // [64][12][1024]
{
    __shared__ float sh_h[HORIZON * 65];
    __shared__ float sh_x[BATCH * 65];

    const int n   = blockIdx.x;   // node (m index of GEMM)
    const int tid = threadIdx.x;

    #pragma unroll
    for (int r = 0; r < 3; r++) {
        const int j = tid + 256 * r;              // 0..767
        float acc = b_hyp[j];
        #pragma unroll
        for (int sp = 0; sp < SPLITK; sp++)
            acc += g_part[((size_t)sp * MTOT + n) * NTOT + j];
        sh_h[(j >> 6) * 65 + (j & 63)] = acc;
    }

    #pragma unroll
    for (int r = 0; r < 16; r++) {
        const int i = tid + 256 * r;              // 0..4095
        const int b = i >> 6, f = i & 63;
        sh_x[b * 65 + f] =
            x_all[((size_t)(b * T_IN + (T_IN - 1)) * MTOT + n) * 64 + f];
    }
    __syncthreads();

    #pragma unroll
    for (int r = 0; r < 3; r++) {
        const int j = tid + 256 * r;
        const int b = j / 12, t = j % 12;
        float acc = 0.0f;
        #pragma unroll
        for (int f = 0; f < 64; f++)
            acc += sh_x[b * 65 + f] * sh_h[t * 65 + f];
        out[(size_t)(b * HORIZON + t) * MTOT + n] = acc;
    }
}

// ---------------- launch ----------------
extern "C" void kernel_launch(void* const* d_in, const int* in_sizes, int n_in,
                              void* d_out, int out_size) {
    const float* output  = (const float*)d_in[0];   // [64,12,1024,64]
    const float* weights = (const float*)d_in[1];   // [1024,36864]
    const float* W_hyp   = (const float*)d_in[2];   // [768,36864]
    const float* b_hyp   = (const float*)d_in[3];   // [768]
    float* out = (float*)d_out;

    cudaFuncSetAttribute(gemm_mma_kernel,
                         cudaFuncAttributeMaxDynamicSharedMemorySize, SMEM_TOTAL);

    const int nA4 = MTOT * K2 / 4;
    const int nB4 = NTOT * K2 / 4;
    convert_kernel<<<(nA4 + 255) / 256, 256>>>(weights, 0, nA4);
    convert_kernel<<<(nB4 + 255) / 256, 256>>>(W_hyp,   1, nB4);

    dim3 grid(MTOT / BM, NTOT / BN, SPLITK);   // (8, 6, 3) = 144 CTAs
    gemm_mma_kernel<<<grid, 256, SMEM_TOTAL>>>();

    epilogue_kernel<<<MTOT, 256>>>(output, b_hyp, out);
}